// round 7
// baseline (speedup 1.0000x reference)
#include <cuda_runtime.h>
#include <cuda_bf16.h>
#include <cstddef>

#define NB   16
#define ND   4
#define NF   481
#define NT   500
#define CH   16
#define NH   32
#define NSEQ (NB * NF)              // 7696
#define PROB_ELEMS (NSEQ * NT)      // 3,848,000
#define H_ELEMS    (NSEQ * NH)      // 246,272

#define GPW 8
#define NGRP (NSEQ / GPW)           // 962 groups of 8 sequences

typedef unsigned long long u64;

// conv output x, layout [gw][t][g][c]  (gw = seq>>3, g = seq&7)
__device__ float g_x2[(size_t)NGRP * NT * 8 * CH];
// fallback sink for h_last
__device__ float g_hdump[H_ELEMS];

// ---------------------------------------------------------------------------
// packed f32x2 helpers
// ---------------------------------------------------------------------------
__device__ __forceinline__ u64 fma2(u64 a, u64 b, u64 c) {
    u64 d;
    asm("fma.rn.f32x2 %0, %1, %2, %3;" : "=l"(d) : "l"(a), "l"(b), "l"(c));
    return d;
}
__device__ __forceinline__ u64 add2(u64 a, u64 b) {
    u64 d;
    asm("add.rn.f32x2 %0, %1, %2;" : "=l"(d) : "l"(a), "l"(b));
    return d;
}
__device__ __forceinline__ u64 pack2(float lo, float hi) {
    u64 d;
    asm("mov.b64 %0, {%1, %2};" : "=l"(d) : "f"(lo), "f"(hi));
    return d;
}
__device__ __forceinline__ void unpack2(u64 v, float& lo, float& hi) {
    asm("mov.b64 {%0, %1}, %2;" : "=f"(lo), "=f"(hi) : "l"(v));
}
__device__ __forceinline__ float sigm(float v) {
    return __fdividef(1.f, 1.f + __expf(-v));
}
__device__ __forceinline__ float tanh_f(float v) {
    return __fdividef(2.f, 1.f + __expf(-2.f * v)) - 1.f;
}

// ---------------------------------------------------------------------------
// Kernel 1: fused conv1(K=9,pad=4)+PReLU -> conv2(K=5,pad=2)+PReLU  (f32x2)
// (unchanged from R6 — measured ~85% of fma2 peak)
// ---------------------------------------------------------------------------
#define FT 32
#define TT 32
#define FIN 44
#define FC1 36

#define W1D 576
#define W2D 1280
#define BD  32

__global__ __launch_bounds__(256, 2) void conv_kernel(
    const float* __restrict__ feat,
    const float* __restrict__ w1, const float* __restrict__ b1,
    const float* __restrict__ a1p,
    const float* __restrict__ w2, const float* __restrict__ b2,
    const float* __restrict__ a2p)
{
    extern __shared__ u64 smu[];
    u64* s_w1d = smu;                  // [576]  duplicated pairs
    u64* s_w2d = smu + W1D;            // [1280]
    u64* s_bd  = s_w2d + W2D;          // [32]
    float* s_in = (float*)(s_bd + BD);         // [ND][FIN][TT]
    float* s_c1 = s_in + ND * FIN * TT;        // [CH][FC1][TT]

    const int tid = threadIdx.x;
    const int t0 = blockIdx.x * TT;
    const int f0 = blockIdx.y * FT;
    const int b  = blockIdx.z;
    const float a1 = a1p[0];
    const float a2 = a2p[0];

    for (int i = tid; i < W1D;  i += 256) { float w = w1[i]; s_w1d[i] = pack2(w, w); }
    for (int i = tid; i < W2D; i += 256)  { float w = w2[i]; s_w2d[i] = pack2(w, w); }
    if (tid < 16)       { float v = b1[tid];      s_bd[tid] = pack2(v, v); }
    else if (tid < 32)  { float v = b2[tid - 16]; s_bd[tid] = pack2(v, v); }

    for (int i = tid; i < ND * FIN * TT; i += 256) {
        int t  = i & (TT - 1);
        int fl = (i / TT) % FIN;
        int d  = i / (TT * FIN);
        int f  = f0 - 6 + fl;
        int tg = t0 + t;
        float v = 0.f;
        if (f >= 0 && f < NF && tg < NT)
            v = feat[((b * ND + d) * NF + f) * NT + tg];
        s_in[i] = v;
    }
    __syncthreads();

    // Stage B: conv1 + PReLU
    for (int u = tid; u < FC1 * 8; u += 256) {
        int tq  = u & 7;
        int f1i = u >> 3;
        int f1  = f0 - 2 + f1i;
        u64 a2r[CH][2];
        if (f1 >= 0 && f1 < NF) {
            #pragma unroll
            for (int c = 0; c < CH; c++) { a2r[c][0] = s_bd[c]; a2r[c][1] = s_bd[c]; }
            #pragma unroll
            for (int d = 0; d < ND; d++)
                #pragma unroll
                for (int k = 0; k < 9; k++) {
                    const u64* vp = (const u64*)&s_in[(d * FIN + f1i + k) * TT + tq * 4];
                    u64 v0 = vp[0], v1 = vp[1];
                    #pragma unroll
                    for (int c = 0; c < CH; c++) {
                        u64 w = s_w1d[(c * ND + d) * 9 + k];
                        a2r[c][0] = fma2(w, v0, a2r[c][0]);
                        a2r[c][1] = fma2(w, v1, a2r[c][1]);
                    }
                }
            #pragma unroll
            for (int c = 0; c < CH; c++)
                #pragma unroll
                for (int hh = 0; hh < 2; hh++) {
                    float x0, x1;
                    unpack2(a2r[c][hh], x0, x1);
                    x0 = x0 >= 0.f ? x0 : a1 * x0;
                    x1 = x1 >= 0.f ? x1 : a1 * x1;
                    a2r[c][hh] = pack2(x0, x1);
                }
        } else {
            #pragma unroll
            for (int c = 0; c < CH; c++) { a2r[c][0] = 0ull; a2r[c][1] = 0ull; }
        }
        #pragma unroll
        for (int c = 0; c < CH; c++) {
            u64* op = (u64*)&s_c1[(c * FC1 + f1i) * TT + tq * 4];
            op[0] = a2r[c][0]; op[1] = a2r[c][1];
        }
    }
    __syncthreads();

    // Stage C: conv2 + PReLU + layout-converted output
    {
        int tq  = tid & 7;
        int f2i = tid >> 3;
        u64 a2r[CH][2];
        #pragma unroll
        for (int c = 0; c < CH; c++) { a2r[c][0] = s_bd[16 + c]; a2r[c][1] = s_bd[16 + c]; }
        #pragma unroll
        for (int ci = 0; ci < CH; ci++)
            #pragma unroll
            for (int k = 0; k < 5; k++) {
                const u64* vp = (const u64*)&s_c1[(ci * FC1 + f2i + k) * TT + tq * 4];
                u64 v0 = vp[0], v1 = vp[1];
                #pragma unroll
                for (int co = 0; co < CH; co++) {
                    u64 w = s_w2d[(co * CH + ci) * 5 + k];
                    a2r[co][0] = fma2(w, v0, a2r[co][0]);
                    a2r[co][1] = fma2(w, v1, a2r[co][1]);
                }
            }
        float ov[CH][4];
        #pragma unroll
        for (int c = 0; c < CH; c++) {
            unpack2(a2r[c][0], ov[c][0], ov[c][1]);
            unpack2(a2r[c][1], ov[c][2], ov[c][3]);
            #pragma unroll
            for (int tw = 0; tw < 4; tw++) {
                float x = ov[c][tw];
                ov[c][tw] = x >= 0.f ? x : a2 * x;
            }
        }
        int f = f0 + f2i;
        if (f < NF) {
            int seq = b * NF + f;
            size_t base = (size_t)(seq >> 3) * NT * 128 + (seq & 7) * 16;
            #pragma unroll
            for (int tw = 0; tw < 4; tw++) {
                int t = t0 + tq * 4 + tw;
                if (t < NT) {
                    float* o = g_x2 + base + (size_t)t * 128;
                    #pragma unroll
                    for (int c4 = 0; c4 < 4; c4++)
                        *(float4*)(o + c4 * 4) = make_float4(
                            ov[c4 * 4 + 0][tw], ov[c4 * 4 + 1][tw],
                            ov[c4 * 4 + 2][tw], ov[c4 * 4 + 3][tw]);
                }
            }
        }
    }
}

// ---------------------------------------------------------------------------
// Kernel 2: GRU, k-split cooperative 2-warp blocks.
// Block = 64 threads = 2 warps, handles 8 sequences (one group gw).
// Warp w: k in [16w,16w+16) of w_hh, c in [8w,8w+8) of w_ih, all 8 seqs.
// After partial exchange, warp w finalizes gates/fc/prob for seqs 4w..4w+3.
// ---------------------------------------------------------------------------
__global__ __launch_bounds__(64) void gru_kernel(
    const float* __restrict__ h0,
    const float* __restrict__ w_ih, const float* __restrict__ w_hh,
    const float* __restrict__ b_ih, const float* __restrict__ b_hh,
    const float* __restrict__ fc_w, const float* __restrict__ fc_b,
    float* __restrict__ prob, float* __restrict__ hlast)
{
    __shared__ float4 s_whhA[NH][NH];     // [k][j] = (wr,wr,wz,wz)   16KB
    __shared__ u64   s_hh[NH][4];         // [k][pair]                1KB
    __shared__ u64   s_part[2][8][32];    // partial accs exchange    4KB
    __shared__ float s_xT[CH][12];        // [c][g] padded            768B

    const int tid  = threadIdx.x;
    const int lane = tid & 31;
    const int wp   = tid >> 5;            // 0 or 1
    const int j    = lane;

    // stage w_hh r/z as duplicated pairs (both warps cooperate)
    for (int i = tid; i < NH * NH; i += 64) {
        int k = i >> 5, jj = i & 31;
        float wr = w_hh[jj * NH + k];
        float wz = w_hh[(NH + jj) * NH + k];
        s_whhA[k][jj] = make_float4(wr, wr, wz, wz);
    }

    const int gw = blockIdx.x;
    const int sbase = gw * GPW;
    const int k0 = wp * 16;
    const int c0 = wp * 8;

    // register weights: w_ih for own c half, w_hh n-gate for own k half
    u64 wxr[8], wxz[8], wxn[8], whn[16];
    #pragma unroll
    for (int c = 0; c < 8; c++) {
        int cg = c0 + c;
        float wr = w_ih[j * CH + cg];
        float wz = w_ih[(NH + j) * CH + cg];
        float wn = w_ih[(2 * NH + j) * CH + cg];
        wxr[c] = pack2(wr, wr); wxz[c] = pack2(wz, wz); wxn[c] = pack2(wn, wn);
    }
    #pragma unroll
    for (int k = 0; k < 16; k++) {
        float wn = w_hh[(2 * NH + j) * NH + k0 + k];
        whn[k] = pack2(wn, wn);
    }

    const float brf  = b_ih[j] + b_hh[j];
    const float bzf  = b_ih[NH + j] + b_hh[NH + j];
    const float bxnf = b_ih[2 * NH + j];
    const float bhnf = b_hh[2 * NH + j];
    const u64 br2  = pack2(brf, brf);
    const u64 bz2  = pack2(bzf, bzf);
    const u64 bxn2 = pack2(bxnf, bxnf);
    const u64 bhn2 = pack2(bhnf, bhnf);
    const float fcwj = fc_w[j];
    const float fcb  = fc_b[0];

    // h0 for own 4 seqs -> registers + s_hh own pairs
    float hreg[4];
    #pragma unroll
    for (int q = 0; q < 4; q++) hreg[q] = h0[(sbase + 4 * wp + q) * NH + j];
    {
        ulonglong2 v;
        v.x = pack2(hreg[0], hreg[1]); v.y = pack2(hreg[2], hreg[3]);
        *(ulonglong2*)&s_hh[j][2 * wp] = v;
    }

    // x: lane -> (g = lane>>2, i = lane&3) covering own c half [c0, c0+8)
    const int lg = lane >> 2, li = lane & 3;
    const float* xptr = g_x2 + (size_t)gw * NT * 128 + lg * 16 + c0 + 2 * li;
    float2 xv = *(const float2*)xptr;

    __syncthreads();

    for (int t = 0; t < NT; t++) {
        // stage own x columns into [c][g]
        s_xT[c0 + 2 * li + 0][lg] = xv.x;
        s_xT[c0 + 2 * li + 1][lg] = xv.y;
        __syncwarp();
        if (t + 1 < NT)
            xv = *(const float2*)(xptr + (size_t)(t + 1) * 128);

        // partial accumulators (biases seeded only into own pairs)
        u64 ar[4], az[4], axn[4], ahn[4];
        if (wp == 0) {
            ar[0] = br2;  ar[1] = br2;  ar[2] = 0;  ar[3] = 0;
            az[0] = bz2;  az[1] = bz2;  az[2] = 0;  az[3] = 0;
            axn[0] = bxn2; axn[1] = bxn2; axn[2] = 0; axn[3] = 0;
            ahn[0] = bhn2; ahn[1] = bhn2; ahn[2] = 0; ahn[3] = 0;
        } else {
            ar[0] = 0;  ar[1] = 0;  ar[2] = br2;  ar[3] = br2;
            az[0] = 0;  az[1] = 0;  az[2] = bz2;  az[3] = bz2;
            axn[0] = 0; axn[1] = 0; axn[2] = bxn2; axn[3] = bxn2;
            ahn[0] = 0; ahn[1] = 0; ahn[2] = bhn2; ahn[3] = bhn2;
        }

        // h @ w_hh^T over own k half
        #pragma unroll
        for (int kk = 0; kk < 16; kk++) {
            int k = k0 + kk;
            ulonglong2 wA = *(const ulonglong2*)&s_whhA[k][j];
            ulonglong2 hA = *(const ulonglong2*)&s_hh[k][0];
            ulonglong2 hB = *(const ulonglong2*)&s_hh[k][2];
            ar[0]  = fma2(wA.x,    hA.x, ar[0]);  ar[1]  = fma2(wA.x,    hA.y, ar[1]);
            ar[2]  = fma2(wA.x,    hB.x, ar[2]);  ar[3]  = fma2(wA.x,    hB.y, ar[3]);
            az[0]  = fma2(wA.y,    hA.x, az[0]);  az[1]  = fma2(wA.y,    hA.y, az[1]);
            az[2]  = fma2(wA.y,    hB.x, az[2]);  az[3]  = fma2(wA.y,    hB.y, az[3]);
            ahn[0] = fma2(whn[kk], hA.x, ahn[0]); ahn[1] = fma2(whn[kk], hA.y, ahn[1]);
            ahn[2] = fma2(whn[kk], hB.x, ahn[2]); ahn[3] = fma2(whn[kk], hB.y, ahn[3]);
        }
        // x @ w_ih^T over own c half
        #pragma unroll
        for (int cc = 0; cc < 8; cc++) {
            const float* r = &s_xT[c0 + cc][0];
            ulonglong2 xA = *(const ulonglong2*)r;
            ulonglong2 xB = *(const ulonglong2*)(r + 4);
            ar[0]  = fma2(wxr[cc], xA.x, ar[0]);  ar[1]  = fma2(wxr[cc], xA.y, ar[1]);
            ar[2]  = fma2(wxr[cc], xB.x, ar[2]);  ar[3]  = fma2(wxr[cc], xB.y, ar[3]);
            az[0]  = fma2(wxz[cc], xA.x, az[0]);  az[1]  = fma2(wxz[cc], xA.y, az[1]);
            az[2]  = fma2(wxz[cc], xB.x, az[2]);  az[3]  = fma2(wxz[cc], xB.y, az[3]);
            axn[0] = fma2(wxn[cc], xA.x, axn[0]); axn[1] = fma2(wxn[cc], xA.y, axn[1]);
            axn[2] = fma2(wxn[cc], xB.x, axn[2]); axn[3] = fma2(wxn[cc], xB.y, axn[3]);
        }

        // send partials for the OTHER warp's pairs
        if (wp == 0) {
            s_part[0][0][lane] = ar[2];  s_part[0][1][lane] = ar[3];
            s_part[0][2][lane] = az[2];  s_part[0][3][lane] = az[3];
            s_part[0][4][lane] = axn[2]; s_part[0][5][lane] = axn[3];
            s_part[0][6][lane] = ahn[2]; s_part[0][7][lane] = ahn[3];
        } else {
            s_part[1][0][lane] = ar[0];  s_part[1][1][lane] = ar[1];
            s_part[1][2][lane] = az[0];  s_part[1][3][lane] = az[1];
            s_part[1][4][lane] = axn[0]; s_part[1][5][lane] = axn[1];
            s_part[1][6][lane] = ahn[0]; s_part[1][7][lane] = ahn[1];
        }
        __syncthreads();

        // combine own pairs
        u64 aR0, aR1, aZ0, aZ1, aXN0, aXN1, aHN0, aHN1;
        if (wp == 0) {
            aR0  = add2(ar[0],  s_part[1][0][lane]); aR1  = add2(ar[1],  s_part[1][1][lane]);
            aZ0  = add2(az[0],  s_part[1][2][lane]); aZ1  = add2(az[1],  s_part[1][3][lane]);
            aXN0 = add2(axn[0], s_part[1][4][lane]); aXN1 = add2(axn[1], s_part[1][5][lane]);
            aHN0 = add2(ahn[0], s_part[1][6][lane]); aHN1 = add2(ahn[1], s_part[1][7][lane]);
        } else {
            aR0  = add2(ar[2],  s_part[0][0][lane]); aR1  = add2(ar[3],  s_part[0][1][lane]);
            aZ0  = add2(az[2],  s_part[0][2][lane]); aZ1  = add2(az[3],  s_part[0][3][lane]);
            aXN0 = add2(axn[2], s_part[0][4][lane]); aXN1 = add2(axn[3], s_part[0][5][lane]);
            aHN0 = add2(ahn[2], s_part[0][6][lane]); aHN1 = add2(ahn[3], s_part[0][7][lane]);
        }

        // gates + hnew for own 4 seqs
        float hnew[4];
        {
            float a0, a1v, z0, z1, x0, x1, hh0, hh1;
            unpack2(aR0, a0, a1v); unpack2(aZ0, z0, z1);
            unpack2(aXN0, x0, x1); unpack2(aHN0, hh0, hh1);
            float r0 = sigm(a0), r1 = sigm(a1v);
            float zz0 = sigm(z0), zz1 = sigm(z1);
            float n0 = tanh_f(fmaf(r0, hh0, x0));
            float n1 = tanh_f(fmaf(r1, hh1, x1));
            hnew[0] = fmaf(zz0, hreg[0] - n0, n0);
            hnew[1] = fmaf(zz1, hreg[1] - n1, n1);
            unpack2(aR1, a0, a1v); unpack2(aZ1, z0, z1);
            unpack2(aXN1, x0, x1); unpack2(aHN1, hh0, hh1);
            r0 = sigm(a0); r1 = sigm(a1v);
            zz0 = sigm(z0); zz1 = sigm(z1);
            n0 = tanh_f(fmaf(r0, hh0, x0));
            n1 = tanh_f(fmaf(r1, hh1, x1));
            hnew[2] = fmaf(zz0, hreg[2] - n0, n0);
            hnew[3] = fmaf(zz1, hreg[3] - n1, n1);
        }

        // store h for own pairs (safe: all s_hh reads were before the bar)
        {
            ulonglong2 v;
            v.x = pack2(hnew[0], hnew[1]); v.y = pack2(hnew[2], hnew[3]);
            *(ulonglong2*)&s_hh[j][2 * wp] = v;
        }
        #pragma unroll
        for (int q = 0; q < 4; q++) hreg[q] = hnew[q];

        // fc + sigmoid via warp butterfly (4 values)
        float pc0 = hnew[0] * fcwj, pc1 = hnew[1] * fcwj;
        float pc2 = hnew[2] * fcwj, pc3 = hnew[3] * fcwj;
        #pragma unroll
        for (int off = 16; off; off >>= 1) {
            pc0 += __shfl_xor_sync(0xffffffffu, pc0, off);
            pc1 += __shfl_xor_sync(0xffffffffu, pc1, off);
            pc2 += __shfl_xor_sync(0xffffffffu, pc2, off);
            pc3 += __shfl_xor_sync(0xffffffffu, pc3, off);
        }
        if (lane == 0) prob[(size_t)(sbase + 4 * wp + 0) * NT + t] = sigm(pc0 + fcb);
        if (lane == 1) prob[(size_t)(sbase + 4 * wp + 1) * NT + t] = sigm(pc1 + fcb);
        if (lane == 2) prob[(size_t)(sbase + 4 * wp + 2) * NT + t] = sigm(pc2 + fcb);
        if (lane == 3) prob[(size_t)(sbase + 4 * wp + 3) * NT + t] = sigm(pc3 + fcb);

        __syncthreads();   // h stores visible before next step's reads
    }

    #pragma unroll
    for (int q = 0; q < 4; q++)
        hlast[(sbase + 4 * wp + q) * NH + j] = hreg[q];
}

// ---------------------------------------------------------------------------
extern "C" void kernel_launch(void* const* d_in, const int* in_sizes, int n_in,
                              void* d_out, int out_size)
{
    const float* feat  = (const float*)d_in[0];
    const float* h0    = (const float*)d_in[1];
    const float* w1    = (const float*)d_in[2];
    const float* b1    = (const float*)d_in[3];
    const float* a1    = (const float*)d_in[4];
    const float* w2    = (const float*)d_in[5];
    const float* b2    = (const float*)d_in[6];
    const float* a2    = (const float*)d_in[7];
    const float* w_ih  = (const float*)d_in[8];
    const float* w_hh  = (const float*)d_in[9];
    const float* b_ih  = (const float*)d_in[10];
    const float* b_hh  = (const float*)d_in[11];
    const float* fc_w  = (const float*)d_in[12];
    const float* fc_b  = (const float*)d_in[13];

    float* prob = (float*)d_out;
    float* hlast;
    if (out_size >= PROB_ELEMS + H_ELEMS) {
        hlast = prob + PROB_ELEMS;
    } else {
        void* p = nullptr;
        cudaGetSymbolAddress(&p, g_hdump);
        hlast = (float*)p;
    }

    const int smem_bytes = (W1D + W2D + BD) * 8 + (ND * FIN * TT + CH * FC1 * TT) * 4;
    cudaFuncSetAttribute(conv_kernel, cudaFuncAttributeMaxDynamicSharedMemorySize,
                         smem_bytes);

    dim3 cgrid((NT + TT - 1) / TT, (NF + FT - 1) / FT, NB);
    conv_kernel<<<cgrid, 256, smem_bytes>>>(feat, w1, b1, a1, w2, b2, a2);

    gru_kernel<<<NGRP, 64>>>(h0, w_ih, w_hh, b_ih, b_hh, fc_w, fc_b,
                             prob, hlast);
}